// round 11
// baseline (speedup 1.0000x reference)
#include <cuda_runtime.h>
#include <cuda_bf16.h>

// LSTM_24936580121326 R11: element-lane packing. State {hA,hB}/{cA,cB} lives
// directly in f32x2 lanes; weights splatted {w,w} in constant. No splat regs,
// target <=128 regs -> 2 CTAs/SM -> 4 warps/SMSP + single wave.

#define T_STEPS 49

typedef unsigned long long u64;

struct WPack {
    // [unit][gate 0=i,1=f,2=g,3=o][colpair q]: {splat(w[2q]), splat(w[2q+1])}
    ulonglong2 w1[8][4][4];   // layer1 W_hh   (i/f/o rows *0.5)
    ulonglong2 w2u[8][4][4];  // layer2 W_ih
    ulonglong2 w2v[8][4][4];  // layer2 W_hh
    u64 wx[8][4];             // layer1 W_ih splats (scaled)
    u64 b1[8][4];             // bias splats (scaled)
    u64 b2[8][4];
    float wlin[8];
    float blin;
};

__device__   WPack g_wtmp;
__constant__ WPack c_w;

__device__ __forceinline__ u64 pack2(float lo, float hi) {
    u64 r; asm("mov.b64 %0, {%1, %2};" : "=l"(r) : "f"(lo), "f"(hi)); return r;
}
__device__ __forceinline__ void unpack2(u64 v, float& lo, float& hi) {
    asm("mov.b64 {%0, %1}, %2;" : "=f"(lo), "=f"(hi) : "l"(v));
}
__device__ __forceinline__ u64 fma2(u64 a, u64 b, u64 c) {
    u64 d; asm("fma.rn.f32x2 %0, %1, %2, %3;" : "=l"(d) : "l"(a), "l"(b), "l"(c)); return d;
}
__device__ __forceinline__ float tanhf_hw(float x) {
    float y; asm("tanh.approx.f32 %0, %1;" : "=f"(y) : "f"(x)); return y;
}
__device__ __forceinline__ float sig_folded(float zh) {   // pre-halved input
    return fmaf(0.5f, tanhf_hw(zh), 0.5f);
}

// ---------------- preproc: splat + scale into g_wtmp ----------------
__global__ void prep_weights_kernel(
    const float* __restrict__ W_ih0, const float* __restrict__ W_hh0,
    const float* __restrict__ b_ih0, const float* __restrict__ b_hh0,
    const float* __restrict__ W_ih1, const float* __restrict__ W_hh1,
    const float* __restrict__ b_ih1, const float* __restrict__ b_hh1,
    const float* __restrict__ W_lin, const float* __restrict__ b_lin)
{
    int tid = threadIdx.x;
    if (tid < 256) {
        int u = tid >> 5, gi = (tid >> 3) & 3, q = (tid >> 1) & 3, half = tid & 1;
        int col = 2 * q + half;
        int row = u + 8 * gi;
        float sc = (gi == 2) ? 1.0f : 0.5f;
        float v; float* p;
        v = sc * W_hh0[row * 8 + col];
        p = (float*)&g_wtmp.w1[u][gi][q];  p[half*2] = v; p[half*2+1] = v;
        v = sc * W_ih1[row * 8 + col];
        p = (float*)&g_wtmp.w2u[u][gi][q]; p[half*2] = v; p[half*2+1] = v;
        v = sc * W_hh1[row * 8 + col];
        p = (float*)&g_wtmp.w2v[u][gi][q]; p[half*2] = v; p[half*2+1] = v;
    }
    if (tid < 32) {
        int u = tid >> 2, gi = tid & 3;
        int row = u + 8 * gi;
        float sc = (gi == 2) ? 1.0f : 0.5f;
        float v; float* p;
        v = sc * W_ih0[row];
        p = (float*)&g_wtmp.wx[u][gi]; p[0] = v; p[1] = v;
        v = sc * (b_ih0[row] + b_hh0[row]);
        p = (float*)&g_wtmp.b1[u][gi]; p[0] = v; p[1] = v;
        v = sc * (b_ih1[row] + b_hh1[row]);
        p = (float*)&g_wtmp.b2[u][gi]; p[0] = v; p[1] = v;
    }
    if (tid < 8)  g_wtmp.wlin[tid] = W_lin[tid];
    if (tid == 0) g_wtmp.blin = b_lin[0];
}

// Scalar activation tail, packed cell state. Accs a* = {zA,zB} per gate.
__device__ __forceinline__ u64 act_unit(
    u64 ai, u64 af, u64 ag, u64 ao, u64& C)
{
    float ziA, ziB, zfA, zfB, zgA, zgB, zoA, zoB;
    unpack2(ai, ziA, ziB); unpack2(af, zfA, zfB);
    unpack2(ag, zgA, zgB); unpack2(ao, zoA, zoB);
    float igA = sig_folded(ziA), igB = sig_folded(ziB);
    float fgA = sig_folded(zfA), fgB = sig_folded(zfB);
    float ggA = tanhf_hw(zgA),   ggB = tanhf_hw(zgB);
    float ogA = sig_folded(zoA), ogB = sig_folded(zoB);
    u64 P = pack2(igA * ggA, igB * ggB);
    u64 F = pack2(fgA, fgB);
    C = fma2(F, C, P);
    float cA, cB; unpack2(C, cA, cB);
    return pack2(ogA * tanhf_hw(cA), ogB * tanhf_hw(cB));
}

// ---------------- fused LSTM: lanes = 2 batch elements ----------------
__global__ void __launch_bounds__(256) lstm_fused_kernel(
    const float* __restrict__ X, float* __restrict__ out, int Bn)
{
    int tid = threadIdx.x;
    int bA = blockIdx.x * 512 + tid;
    int bB = bA + 256;
    bool vA = bA < Bn, vB = bB < Bn;

    u64 H1[8], H2[8];   // {hA, hB}
    u64 C1[8], C2[8];   // {cA, cB}
    u64 zero = pack2(0.f, 0.f);
#pragma unroll
    for (int u = 0; u < 8; ++u) { H1[u] = H2[u] = C1[u] = C2[u] = zero; }

    const float* __restrict__ xpA = X + (long long)(vA ? bA : 0) * T_STEPS;
    const long long offB = vB ? (long long)(bB - bA) * T_STEPS : 0;

#pragma unroll 1
    for (int t = 0; t < T_STEPS; ++t) {
        u64 xx = pack2(__ldg(xpA + t), __ldg(xpA + offB + t));

        // ---------- layer 1 ----------
        u64 Hn1[8];
#pragma unroll
        for (int u = 0; u < 8; ++u) {
            u64 ai = fma2(c_w.wx[u][0], xx, c_w.b1[u][0]);
            u64 af = fma2(c_w.wx[u][1], xx, c_w.b1[u][1]);
            u64 ag = fma2(c_w.wx[u][2], xx, c_w.b1[u][2]);
            u64 ao = fma2(c_w.wx[u][3], xx, c_w.b1[u][3]);
#pragma unroll
            for (int q = 0; q < 4; ++q) {
                u64 hL = H1[2*q], hH = H1[2*q+1];
                ulonglong2 Wi = c_w.w1[u][0][q];
                ai = fma2(Wi.x, hL, ai); ai = fma2(Wi.y, hH, ai);
                ulonglong2 Wf = c_w.w1[u][1][q];
                af = fma2(Wf.x, hL, af); af = fma2(Wf.y, hH, af);
                ulonglong2 Wg = c_w.w1[u][2][q];
                ag = fma2(Wg.x, hL, ag); ag = fma2(Wg.y, hH, ag);
                ulonglong2 Wo = c_w.w1[u][3][q];
                ao = fma2(Wo.x, hL, ao); ao = fma2(Wo.y, hH, ao);
            }
            Hn1[u] = act_unit(ai, af, ag, ao, C1[u]);
        }

        // ---------- layer 2 ----------
        u64 Hn2[8];
#pragma unroll
        for (int u = 0; u < 8; ++u) {
            u64 ai = c_w.b2[u][0];
            u64 af = c_w.b2[u][1];
            u64 ag = c_w.b2[u][2];
            u64 ao = c_w.b2[u][3];
#pragma unroll
            for (int q = 0; q < 4; ++q) {
                u64 hL = Hn1[2*q], hH = Hn1[2*q+1];
                ulonglong2 Ui = c_w.w2u[u][0][q];
                ai = fma2(Ui.x, hL, ai); ai = fma2(Ui.y, hH, ai);
                ulonglong2 Uf = c_w.w2u[u][1][q];
                af = fma2(Uf.x, hL, af); af = fma2(Uf.y, hH, af);
                ulonglong2 Ug = c_w.w2u[u][2][q];
                ag = fma2(Ug.x, hL, ag); ag = fma2(Ug.y, hH, ag);
                ulonglong2 Uo = c_w.w2u[u][3][q];
                ao = fma2(Uo.x, hL, ao); ao = fma2(Uo.y, hH, ao);
            }
#pragma unroll
            for (int q = 0; q < 4; ++q) {
                u64 hL = H2[2*q], hH = H2[2*q+1];
                ulonglong2 Vi = c_w.w2v[u][0][q];
                ai = fma2(Vi.x, hL, ai); ai = fma2(Vi.y, hH, ai);
                ulonglong2 Vf = c_w.w2v[u][1][q];
                af = fma2(Vf.x, hL, af); af = fma2(Vf.y, hH, af);
                ulonglong2 Vg = c_w.w2v[u][2][q];
                ag = fma2(Vg.x, hL, ag); ag = fma2(Vg.y, hH, ag);
                ulonglong2 Vo = c_w.w2v[u][3][q];
                ao = fma2(Vo.x, hL, ao); ao = fma2(Vo.y, hH, ao);
            }
            Hn2[u] = act_unit(ai, af, ag, ao, C2[u]);
        }

#pragma unroll
        for (int u = 0; u < 8; ++u) { H1[u] = Hn1[u]; H2[u] = Hn2[u]; }
    }

    // ---------- relu -> linear -> relu ----------
    float accA = c_w.blin, accB = c_w.blin;
#pragma unroll
    for (int u = 0; u < 8; ++u) {
        float hA, hB;
        unpack2(H2[u], hA, hB);
        accA = fmaf(c_w.wlin[u], fmaxf(hA, 0.0f), accA);
        accB = fmaf(c_w.wlin[u], fmaxf(hB, 0.0f), accB);
    }
    if (vA) out[bA] = fmaxf(accA, 0.0f);
    if (vB) out[bB] = fmaxf(accB, 0.0f);
}

extern "C" void kernel_launch(void* const* d_in, const int* in_sizes, int n_in,
                              void* d_out, int out_size) {
    const float* X     = (const float*)d_in[0];
    const float* W_ih0 = (const float*)d_in[1];
    const float* W_hh0 = (const float*)d_in[2];
    const float* b_ih0 = (const float*)d_in[3];
    const float* b_hh0 = (const float*)d_in[4];
    const float* W_ih1 = (const float*)d_in[5];
    const float* W_hh1 = (const float*)d_in[6];
    const float* b_ih1 = (const float*)d_in[7];
    const float* b_hh1 = (const float*)d_in[8];
    const float* W_lin = (const float*)d_in[9];
    const float* b_lin = (const float*)d_in[10];

    int Bn = out_size;

    prep_weights_kernel<<<1, 256>>>(
        W_ih0, W_hh0, b_ih0, b_hh0,
        W_ih1, W_hh1, b_ih1, b_hh1, W_lin, b_lin);

    void* src = nullptr;
    cudaGetSymbolAddress(&src, g_wtmp);
    cudaMemcpyToSymbolAsync(c_w, src, sizeof(WPack), 0,
                            cudaMemcpyDeviceToDevice, 0);

    int blocks = (Bn + 511) / 512;
    lstm_fused_kernel<<<blocks, 256>>>(X, (float*)d_out, Bn);
}

// round 12
// speedup vs baseline: 2.0105x; 2.0105x over previous
#include <cuda_runtime.h>
#include <cuda_bf16.h>

// LSTM_24936580121326 R12: R9 base (constant gate-pair f32x2, 2 elem/thread)
// + cross-layer software pipelining: inside step t, layer1(t) and layer2(t-1)
// both read the SAME old H1 state and are fully independent -> 2x chain ILP,
// 4 activation tails in flight. Prologue = L1(t=0), epilogue = L2(t=48).

#define T_STEPS 49

typedef unsigned long long u64;

struct WPack {
    ulonglong2 w1if[8][4];   // layer1 W_hh rows (i,f) scaled 0.5
    ulonglong2 w1go[8][4];   // layer1 W_hh rows (g unscaled, o 0.5)
    ulonglong2 w2uif[8][4];  // layer2 W_ih
    ulonglong2 w2ugo[8][4];
    ulonglong2 w2vif[8][4];  // layer2 W_hh
    ulonglong2 w2vgo[8][4];
    u64 wx_if[8], wx_go[8];  // layer1 W_ih (input dim 1)
    u64 b1if[8], b1go[8];
    u64 b2if[8], b2go[8];
    float wlin[8];
    float blin;
};

__device__   WPack g_wtmp;
__constant__ WPack c_w;

__device__ __forceinline__ u64 pack2(float lo, float hi) {
    u64 r; asm("mov.b64 %0, {%1, %2};" : "=l"(r) : "f"(lo), "f"(hi)); return r;
}
__device__ __forceinline__ void unpack2(u64 v, float& lo, float& hi) {
    asm("mov.b64 {%0, %1}, %2;" : "=f"(lo), "=f"(hi) : "l"(v));
}
__device__ __forceinline__ u64 fma2(u64 a, u64 b, u64 c) {
    u64 d; asm("fma.rn.f32x2 %0, %1, %2, %3;" : "=l"(d) : "l"(a), "l"(b), "l"(c)); return d;
}
__device__ __forceinline__ float tanhf_hw(float x) {
    float y; asm("tanh.approx.f32 %0, %1;" : "=f"(y) : "f"(x)); return y;
}
__device__ __forceinline__ float sig_folded(float zh) {   // pre-halved input
    return fmaf(0.5f, tanhf_hw(zh), 0.5f);
}

// ---------------- preproc (identical to R9) ----------------
__global__ void prep_weights_kernel(
    const float* __restrict__ W_ih0, const float* __restrict__ W_hh0,
    const float* __restrict__ b_ih0, const float* __restrict__ b_hh0,
    const float* __restrict__ W_ih1, const float* __restrict__ W_hh1,
    const float* __restrict__ b_ih1, const float* __restrict__ b_hh1,
    const float* __restrict__ W_lin, const float* __restrict__ b_lin)
{
    int tid = threadIdx.x;
    if (tid < 128) {
        int u = tid >> 4, q = (tid >> 2) & 3, s = tid & 3;
        int col = 2 * q + (s >> 1);
        int sel = s & 1;
        int idx = (u * 4 + q) * 4 + s;
        int gIF = u + 8 * sel;           // i or f
        int gGO = u + 16 + 8 * sel;      // g or o
        float scGO = sel ? 0.5f : 1.0f;
        ((float*)g_wtmp.w1if)[idx]  = 0.5f * W_hh0[gIF * 8 + col];
        ((float*)g_wtmp.w1go)[idx]  = scGO * W_hh0[gGO * 8 + col];
        ((float*)g_wtmp.w2uif)[idx] = 0.5f * W_ih1[gIF * 8 + col];
        ((float*)g_wtmp.w2ugo)[idx] = scGO * W_ih1[gGO * 8 + col];
        ((float*)g_wtmp.w2vif)[idx] = 0.5f * W_hh1[gIF * 8 + col];
        ((float*)g_wtmp.w2vgo)[idx] = scGO * W_hh1[gGO * 8 + col];
    }
    if (tid < 8) {
        int u = tid;
        float* p;
        p = (float*)g_wtmp.wx_if; p[2*u] = 0.5f * W_ih0[u];      p[2*u+1] = 0.5f * W_ih0[u+8];
        p = (float*)g_wtmp.wx_go; p[2*u] =        W_ih0[u+16];   p[2*u+1] = 0.5f * W_ih0[u+24];
        p = (float*)g_wtmp.b1if;  p[2*u] = 0.5f*(b_ih0[u]+b_hh0[u]);
                                  p[2*u+1] = 0.5f*(b_ih0[u+8]+b_hh0[u+8]);
        p = (float*)g_wtmp.b1go;  p[2*u] =       (b_ih0[u+16]+b_hh0[u+16]);
                                  p[2*u+1] = 0.5f*(b_ih0[u+24]+b_hh0[u+24]);
        p = (float*)g_wtmp.b2if;  p[2*u] = 0.5f*(b_ih1[u]+b_hh1[u]);
                                  p[2*u+1] = 0.5f*(b_ih1[u+8]+b_hh1[u+8]);
        p = (float*)g_wtmp.b2go;  p[2*u] =       (b_ih1[u+16]+b_hh1[u+16]);
                                  p[2*u+1] = 0.5f*(b_ih1[u+24]+b_hh1[u+24]);
        g_wtmp.wlin[u] = W_lin[u];
    }
    if (tid == 0) g_wtmp.blin = b_lin[0];
}

// Scalar activation tail for one element: accs {zi,zf},{zg,zo}; scalar c.
__device__ __forceinline__ u64 act_one(u64 aif, u64 ago, float& c)
{
    float zi, zf, zg, zo;
    unpack2(aif, zi, zf);
    unpack2(ago, zg, zo);
    float ig = sig_folded(zi), fg = sig_folded(zf);
    float gg = tanhf_hw(zg),  og = sig_folded(zo);
    c = fmaf(fg, c, ig * gg);
    float h = og * tanhf_hw(c);
    return pack2(h, h);                 // {h,h} splat
}

// ---------------- fused LSTM: pipelined layers, 2 elements/thread ----------
__global__ void __launch_bounds__(256) lstm_fused_kernel(
    const float* __restrict__ X, float* __restrict__ out, int Bn)
{
    int tid  = threadIdx.x;
    int bA = blockIdx.x * 512 + tid;
    int bB = bA + 256;
    bool vA = bA < Bn, vB = bB < Bn;

    u64 H1A[8], H1B[8], H2A[8], H2B[8];   // {h,h} splats
    float c1A[8], c1B[8], c2A[8], c2B[8];
    u64 zero = pack2(0.f, 0.f);
#pragma unroll
    for (int u = 0; u < 8; ++u) {
        H1A[u] = H1B[u] = H2A[u] = H2B[u] = zero;
        c1A[u] = c1B[u] = c2A[u] = c2B[u] = 0.f;
    }

    const float* __restrict__ xpA = X + (long long)(vA ? bA : 0) * T_STEPS;
    const float* __restrict__ xpB = X + (long long)(vB ? bB : 0) * T_STEPS;

    // ---------------- prologue: layer1 at t = 0 (h1 = 0) ----------------
    {
        float xA = __ldg(xpA), xB = __ldg(xpB);
        u64 xxA = pack2(xA, xA), xxB = pack2(xB, xB);
#pragma unroll
        for (int u = 0; u < 8; ++u) {
            u64 wxi = c_w.wx_if[u], wxg = c_w.wx_go[u];
            u64 bi  = c_w.b1if[u],  bg  = c_w.b1go[u];
            H1A[u] = act_one(fma2(wxi, xxA, bi), fma2(wxg, xxA, bg), c1A[u]);
            H1B[u] = act_one(fma2(wxi, xxB, bi), fma2(wxg, xxB, bg), c1B[u]);
        }
    }

    // ------------- main loop: t = 1..48, L1(t) || L2(t-1) ---------------
#pragma unroll 1
    for (int t = 1; t < T_STEPS; ++t) {
        float xA = __ldg(xpA + t), xB = __ldg(xpB + t);
        u64 xxA = pack2(xA, xA), xxB = pack2(xB, xB);

        u64 Hn1A[8], Hn1B[8], Hn2A[8], Hn2B[8];
#pragma unroll
        for (int u = 0; u < 8; ++u) {
            // ---- layer 1 accumulators (read old H1) ----
            u64 a1iA = fma2(c_w.wx_if[u], xxA, c_w.b1if[u]);
            u64 a1gA = fma2(c_w.wx_go[u], xxA, c_w.b1go[u]);
            u64 a1iB = fma2(c_w.wx_if[u], xxB, c_w.b1if[u]);
            u64 a1gB = fma2(c_w.wx_go[u], xxB, c_w.b1go[u]);
            // ---- layer 2 accumulators (read old H1 as input, old H2) ----
            u64 a2iA = c_w.b2if[u], a2gA = c_w.b2go[u];
            u64 a2iB = c_w.b2if[u], a2gB = c_w.b2go[u];
#pragma unroll
            for (int q = 0; q < 4; ++q) {
                u64 h1L_A = H1A[2*q], h1H_A = H1A[2*q+1];
                u64 h1L_B = H1B[2*q], h1H_B = H1B[2*q+1];
                // layer1 W_hh
                ulonglong2 wi = c_w.w1if[u][q];
                ulonglong2 wg = c_w.w1go[u][q];
                a1iA = fma2(wi.x, h1L_A, a1iA); a1iA = fma2(wi.y, h1H_A, a1iA);
                a1gA = fma2(wg.x, h1L_A, a1gA); a1gA = fma2(wg.y, h1H_A, a1gA);
                a1iB = fma2(wi.x, h1L_B, a1iB); a1iB = fma2(wi.y, h1H_B, a1iB);
                a1gB = fma2(wg.x, h1L_B, a1gB); a1gB = fma2(wg.y, h1H_B, a1gB);
                // layer2 W_ih (input = old H1)
                ulonglong2 ui = c_w.w2uif[u][q];
                ulonglong2 ug = c_w.w2ugo[u][q];
                a2iA = fma2(ui.x, h1L_A, a2iA); a2iA = fma2(ui.y, h1H_A, a2iA);
                a2gA = fma2(ug.x, h1L_A, a2gA); a2gA = fma2(ug.y, h1H_A, a2gA);
                a2iB = fma2(ui.x, h1L_B, a2iB); a2iB = fma2(ui.y, h1H_B, a2iB);
                a2gB = fma2(ug.x, h1L_B, a2gB); a2gB = fma2(ug.y, h1H_B, a2gB);
                // layer2 W_hh (old H2)
                u64 h2L_A = H2A[2*q], h2H_A = H2A[2*q+1];
                u64 h2L_B = H2B[2*q], h2H_B = H2B[2*q+1];
                ulonglong2 vi = c_w.w2vif[u][q];
                ulonglong2 vg = c_w.w2vgo[u][q];
                a2iA = fma2(vi.x, h2L_A, a2iA); a2iA = fma2(vi.y, h2H_A, a2iA);
                a2gA = fma2(vg.x, h2L_A, a2gA); a2gA = fma2(vg.y, h2H_A, a2gA);
                a2iB = fma2(vi.x, h2L_B, a2iB); a2iB = fma2(vi.y, h2H_B, a2iB);
                a2gB = fma2(vg.x, h2L_B, a2gB); a2gB = fma2(vg.y, h2H_B, a2gB);
            }
            // four independent activation tails
            Hn1A[u] = act_one(a1iA, a1gA, c1A[u]);
            Hn2A[u] = act_one(a2iA, a2gA, c2A[u]);
            Hn1B[u] = act_one(a1iB, a1gB, c1B[u]);
            Hn2B[u] = act_one(a2iB, a2gB, c2B[u]);
        }
#pragma unroll
        for (int u = 0; u < 8; ++u) {
            H1A[u] = Hn1A[u]; H1B[u] = Hn1B[u];
            H2A[u] = Hn2A[u]; H2B[u] = Hn2B[u];
        }
    }

    // ---------------- epilogue: layer2 at t = 48 ----------------
    u64 HfA[8], HfB[8];
#pragma unroll
    for (int u = 0; u < 8; ++u) {
        u64 a2iA = c_w.b2if[u], a2gA = c_w.b2go[u];
        u64 a2iB = c_w.b2if[u], a2gB = c_w.b2go[u];
#pragma unroll
        for (int q = 0; q < 4; ++q) {
            u64 h1L_A = H1A[2*q], h1H_A = H1A[2*q+1];
            u64 h1L_B = H1B[2*q], h1H_B = H1B[2*q+1];
            ulonglong2 ui = c_w.w2uif[u][q];
            ulonglong2 ug = c_w.w2ugo[u][q];
            a2iA = fma2(ui.x, h1L_A, a2iA); a2iA = fma2(ui.y, h1H_A, a2iA);
            a2gA = fma2(ug.x, h1L_A, a2gA); a2gA = fma2(ug.y, h1H_A, a2gA);
            a2iB = fma2(ui.x, h1L_B, a2iB); a2iB = fma2(ui.y, h1H_B, a2iB);
            a2gB = fma2(ug.x, h1L_B, a2gB); a2gB = fma2(ug.y, h1H_B, a2gB);
            u64 h2L_A = H2A[2*q], h2H_A = H2A[2*q+1];
            u64 h2L_B = H2B[2*q], h2H_B = H2B[2*q+1];
            ulonglong2 vi = c_w.w2vif[u][q];
            ulonglong2 vg = c_w.w2vgo[u][q];
            a2iA = fma2(vi.x, h2L_A, a2iA); a2iA = fma2(vi.y, h2H_A, a2iA);
            a2gA = fma2(vg.x, h2L_A, a2gA); a2gA = fma2(vg.y, h2H_A, a2gA);
            a2iB = fma2(vi.x, h2L_B, a2iB); a2iB = fma2(vi.y, h2H_B, a2iB);
            a2gB = fma2(vg.x, h2L_B, a2gB); a2gB = fma2(vg.y, h2H_B, a2gB);
        }
        HfA[u] = act_one(a2iA, a2gA, c2A[u]);
        HfB[u] = act_one(a2iB, a2gB, c2B[u]);
    }

    // ---------------- relu -> linear -> relu ----------------
    float accA = c_w.blin, accB = c_w.blin;
#pragma unroll
    for (int u = 0; u < 8; ++u) {
        float hA, hB, d;
        unpack2(HfA[u], hA, d);
        unpack2(HfB[u], hB, d);
        accA = fmaf(c_w.wlin[u], fmaxf(hA, 0.0f), accA);
        accB = fmaf(c_w.wlin[u], fmaxf(hB, 0.0f), accB);
    }
    if (vA) out[bA] = fmaxf(accA, 0.0f);
    if (vB) out[bB] = fmaxf(accB, 0.0f);
}

extern "C" void kernel_launch(void* const* d_in, const int* in_sizes, int n_in,
                              void* d_out, int out_size) {
    const float* X     = (const float*)d_in[0];
    const float* W_ih0 = (const float*)d_in[1];
    const float* W_hh0 = (const float*)d_in[2];
    const float* b_ih0 = (const float*)d_in[3];
    const float* b_hh0 = (const float*)d_in[4];
    const float* W_ih1 = (const float*)d_in[5];
    const float* W_hh1 = (const float*)d_in[6];
    const float* b_ih1 = (const float*)d_in[7];
    const float* b_hh1 = (const float*)d_in[8];
    const float* W_lin = (const float*)d_in[9];
    const float* b_lin = (const float*)d_in[10];

    int Bn = out_size;

    prep_weights_kernel<<<1, 256>>>(
        W_ih0, W_hh0, b_ih0, b_hh0,
        W_ih1, W_hh1, b_ih1, b_hh1, W_lin, b_lin);

    void* src = nullptr;
    cudaGetSymbolAddress(&src, g_wtmp);
    cudaMemcpyToSymbolAsync(c_w, src, sizeof(WPack), 0,
                            cudaMemcpyDeviceToDevice, 0);

    int blocks = (Bn + 511) / 512;
    lstm_fused_kernel<<<blocks, 256>>>(X, (float*)d_out, Bn);
}